// round 2
// baseline (speedup 1.0000x reference)
#include <cuda_runtime.h>
#include <cuda_bf16.h>

// Problem constants (B=64, T=128, N=128, K_SUP=8, E=512, steps=10)
#define M_ROWS   8192          // B*T
#define EDIM     512
#define G4       2048          // 4*E
#define NKS      1024          // N*K_SUP
#define NBATCH   64
#define NSTEPS   10

// ---------------- scratch (device globals; no allocation allowed) ------------
__device__ float g_xW[(size_t)M_ROWS * G4];       // 64 MB
__device__ float g_gates[(size_t)M_ROWS * G4];    // 64 MB
__device__ float g_h[(size_t)M_ROWS * EDIM];      // 16 MB
__device__ float g_c[(size_t)M_ROWS * EDIM];      // 16 MB
__device__ float g_scores[(size_t)M_ROWS * NKS];  // 32 MB
__device__ float g_r[(size_t)M_ROWS * EDIM];      // 16 MB

// ---------------- tiled fp32 GEMM: C = A*B(^T) [+Cadd] [+bias] --------------
// A: M x K, row-major (K contiguous)
// BNT=true : B is N x K row-major (C[m,n] = sum_k A[m,k]*B[n,k])   -> "NT"
// BNT=false: B is K x N row-major (C[m,n] = sum_k A[m,k]*B[k,n])   -> "NN"
// Batched via blockIdx.z with element strides aB/bB/cB.
#define BM 128
#define BN 128
#define BKT 16

template <bool BNT>
__global__ __launch_bounds__(256)
void gemm_tile(const float* __restrict__ A, const float* __restrict__ B,
               float* __restrict__ C, const float* __restrict__ Cadd,
               const float* __restrict__ bias1, const float* __restrict__ bias2,
               int M, int N, int K,
               long long aB, long long bB, long long cB)
{
    __shared__ float As[BKT][BM + 4];
    __shared__ float Bs[BKT][BN + 4];

    const int tid = threadIdx.x;           // 0..255
    const int bx = blockIdx.x, by = blockIdx.y, bz = blockIdx.z;

    A += (long long)bz * aB + (long long)by * BM * K;
    if (BNT) B += (long long)bz * bB + (long long)bx * BN * K;
    else     B += (long long)bz * bB + bx * BN;
    C    += (long long)bz * cB;

    const int ty = tid >> 4;               // 0..15 (row group)
    const int tx = tid & 15;               // 0..15 (col group)

    float acc[8][8];
    #pragma unroll
    for (int i = 0; i < 8; i++)
        #pragma unroll
        for (int j = 0; j < 8; j++) acc[i][j] = 0.f;

    for (int k0 = 0; k0 < K; k0 += BKT) {
        // load A tile (128x16, k-contiguous), transpose into As[k][m]
        #pragma unroll
        for (int l = 0; l < 2; l++) {
            int f = tid + l * 256;         // 0..511 float4 slots
            int r = f >> 2;                // 0..127
            int kg = (f & 3) * 4;          // 0,4,8,12
            float4 v = *(const float4*)(A + (long long)r * K + k0 + kg);
            As[kg + 0][r] = v.x; As[kg + 1][r] = v.y;
            As[kg + 2][r] = v.z; As[kg + 3][r] = v.w;
        }
        if (BNT) {
            #pragma unroll
            for (int l = 0; l < 2; l++) {
                int f = tid + l * 256;
                int r = f >> 2;
                int kg = (f & 3) * 4;
                float4 v = *(const float4*)(B + (long long)r * K + k0 + kg);
                Bs[kg + 0][r] = v.x; Bs[kg + 1][r] = v.y;
                Bs[kg + 2][r] = v.z; Bs[kg + 3][r] = v.w;
            }
        } else {
            #pragma unroll
            for (int l = 0; l < 2; l++) {
                int f = tid + l * 256;
                int r = f >> 5;            // 0..15 (k row)
                int cg = (f & 31) * 4;     // 0..124
                float4 v = *(const float4*)(B + (long long)(k0 + r) * N + cg);
                *(float4*)&Bs[r][cg] = v;
            }
        }
        __syncthreads();

        #pragma unroll
        for (int kk = 0; kk < BKT; kk++) {
            float4 a0 = *(const float4*)&As[kk][ty * 8];
            float4 a1 = *(const float4*)&As[kk][ty * 8 + 4];
            float4 b0 = *(const float4*)&Bs[kk][tx * 8];
            float4 b1 = *(const float4*)&Bs[kk][tx * 8 + 4];
            float a[8] = {a0.x, a0.y, a0.z, a0.w, a1.x, a1.y, a1.z, a1.w};
            float b[8] = {b0.x, b0.y, b0.z, b0.w, b1.x, b1.y, b1.z, b1.w};
            #pragma unroll
            for (int i = 0; i < 8; i++)
                #pragma unroll
                for (int j = 0; j < 8; j++)
                    acc[i][j] = fmaf(a[i], b[j], acc[i][j]);
        }
        __syncthreads();
    }

    // epilogue
    const int gr = by * BM + ty * 8;
    const int gc = bx * BN + tx * 8;
    #pragma unroll
    for (int i = 0; i < 8; i++) {
        long long idx = (long long)(gr + i) * N + gc;
        float v[8];
        #pragma unroll
        for (int j = 0; j < 8; j++) {
            float t = acc[i][j];
            if (Cadd)  t += Cadd[idx + j];
            if (bias1) t += bias1[gc + j];
            if (bias2) t += bias2[gc + j];
            v[j] = t;
        }
        *(float4*)(C + idx)     = make_float4(v[0], v[1], v[2], v[3]);
        *(float4*)(C + idx + 4) = make_float4(v[4], v[5], v[6], v[7]);
    }
}

// ---------------- softmax over rows of 1024 ---------------------------------
__global__ void softmax1024(float* __restrict__ s)
{
    __shared__ float red[8];
    float* p = s + (size_t)blockIdx.x * NKS;
    const int tid = threadIdx.x;           // 256 threads, 4 elems each

    float v[4];
    float m = -1e30f;
    #pragma unroll
    for (int i = 0; i < 4; i++) { v[i] = p[tid + i * 256]; m = fmaxf(m, v[i]); }
    #pragma unroll
    for (int o = 16; o > 0; o >>= 1) m = fmaxf(m, __shfl_xor_sync(0xffffffffu, m, o));
    if ((tid & 31) == 0) red[tid >> 5] = m;
    __syncthreads();
    float bm = -1e30f;
    #pragma unroll
    for (int i = 0; i < 8; i++) bm = fmaxf(bm, red[i]);
    __syncthreads();

    float sum = 0.f;
    #pragma unroll
    for (int i = 0; i < 4; i++) { v[i] = __expf(v[i] - bm); sum += v[i]; }
    #pragma unroll
    for (int o = 16; o > 0; o >>= 1) sum += __shfl_xor_sync(0xffffffffu, sum, o);
    if ((tid & 31) == 0) red[tid >> 5] = sum;
    __syncthreads();
    float tot = 0.f;
    #pragma unroll
    for (int i = 0; i < 8; i++) tot += red[i];
    float inv = 1.f / tot;
    #pragma unroll
    for (int i = 0; i < 4; i++) p[tid + i * 256] = v[i] * inv;
}

// ---------------- fused LSTM pointwise --------------------------------------
__global__ void lstm_pw(const float* __restrict__ gates, const float* __restrict__ x,
                        const float* __restrict__ r, float* __restrict__ h,
                        float* __restrict__ c)
{
    long long idx = (long long)blockIdx.x * blockDim.x + threadIdx.x;
    int m = (int)(idx >> 9);               // /512
    int e = (int)(idx & 511);
    const float* grow = gates + (long long)m * G4;
    float gi = grow[e];
    float gf = grow[512 + e];
    float gg = grow[1024 + e];
    float go = grow[1536 + e];
    float cp = c[idx];
    float si = 1.f / (1.f + __expf(-gi));
    float sf = 1.f / (1.f + __expf(-gf));
    float so = 1.f / (1.f + __expf(-go));
    float cn = sf * cp + si * tanhf(gg);
    float hn = so * tanhf(cn) + x[idx] + r[idx];
    c[idx] = cn;
    h[idx] = hn;
}

// ---------------- launch ----------------------------------------------------
extern "C" void kernel_launch(void* const* d_in, const int* in_sizes, int n_in,
                              void* d_out, int out_size)
{
    const float* targets = (const float*)d_in[0];   // [8192, 512]
    const float* sup     = (const float*)d_in[1];   // [64, 1024, 512]
    const float* W_ih    = (const float*)d_in[2];   // [2048, 512]
    const float* W_hh    = (const float*)d_in[3];   // [2048, 512]
    const float* b_ih    = (const float*)d_in[4];   // [2048]
    const float* b_hh    = (const float*)d_in[5];   // [2048]
    float* out = (float*)d_out;

    float *xW, *gates, *h, *c, *scores, *r;
    cudaGetSymbolAddress((void**)&xW, g_xW);
    cudaGetSymbolAddress((void**)&gates, g_gates);
    cudaGetSymbolAddress((void**)&h, g_h);
    cudaGetSymbolAddress((void**)&c, g_c);
    cudaGetSymbolAddress((void**)&scores, g_scores);
    cudaGetSymbolAddress((void**)&r, g_r);

    cudaMemsetAsync(h, 0, (size_t)M_ROWS * EDIM * sizeof(float));
    cudaMemsetAsync(c, 0, (size_t)M_ROWS * EDIM * sizeof(float));

    dim3 blk(256);

    // xW = x @ W_ih^T + b_ih + b_hh   (loop-invariant, computed once)
    gemm_tile<true><<<dim3(G4 / BN, M_ROWS / BM, 1), blk>>>(
        targets, W_ih, xW, nullptr, b_ih, b_hh, M_ROWS, G4, EDIM, 0, 0, 0);

    for (int s = 0; s < NSTEPS; s++) {
        // gates = xW + h_prev @ W_hh^T
        gemm_tile<true><<<dim3(G4 / BN, M_ROWS / BM, 1), blk>>>(
            h, W_hh, gates, xW, nullptr, nullptr, M_ROWS, G4, EDIM, 0, 0, 0);

        // scores[b] = h_prev[b] @ sup[b]^T   (batched NT, 64 batches)
        gemm_tile<true><<<dim3(NKS / BN, 128 / BM, NBATCH), blk>>>(
            h, sup, scores, nullptr, nullptr, nullptr,
            128, NKS, EDIM,
            (long long)128 * EDIM, (long long)NKS * EDIM, (long long)128 * NKS);

        // softmax over the 1024 support slots
        softmax1024<<<M_ROWS, 256>>>(scores);

        // r[b] = attn[b] @ sup[b]   (batched NN)
        gemm_tile<false><<<dim3(EDIM / BN, 128 / BM, NBATCH), blk>>>(
            scores, sup, r, nullptr, nullptr, nullptr,
            128, EDIM, NKS,
            (long long)128 * NKS, (long long)NKS * EDIM, (long long)128 * EDIM);

        // pointwise LSTM cell + residual adds
        lstm_pw<<<(M_ROWS * EDIM) / 256, 256>>>(gates, targets, r, h, c);
    }

    cudaMemcpyAsync(out, h, (size_t)M_ROWS * EDIM * sizeof(float),
                    cudaMemcpyDeviceToDevice);
}

// round 4
// speedup vs baseline: 1.0704x; 1.0704x over previous
#include <cuda_runtime.h>
#include <cuda_bf16.h>
#include <cstdint>

// Problem constants (B=64, T=128, N=128, K_SUP=8, E=512, steps=10)
#define M_ROWS   8192          // B*T
#define EDIM     512
#define G4       2048          // 4*E
#define NKS      1024          // N*K_SUP
#define NBATCH   64
#define NSTEPS   10

// ---------------- scratch (device globals; no allocation allowed) ------------
__device__ float g_xW[(size_t)M_ROWS * G4];       // 64 MB
__device__ float g_gates[(size_t)M_ROWS * G4];    // 64 MB
__device__ float g_h[(size_t)M_ROWS * EDIM];      // 16 MB
__device__ float g_c[(size_t)M_ROWS * EDIM];      // 16 MB
__device__ float g_scores[(size_t)M_ROWS * NKS];  // 32 MB
__device__ float g_r[(size_t)M_ROWS * EDIM];      // 16 MB

// ---------------- 3xTF32 tensor-core GEMM -----------------------------------
// C = A * B(^T) [+Cadd] [+bias1+bias2], fp32-equivalent accuracy via
// hi/lo mantissa split:  a*b ~= a_hi*b_hi + a_hi*b_lo + a_lo*b_hi.
// A: M x K row-major.  BNT=true: B is N x K row-major ("NT").
//                      BNT=false: B is K x N row-major ("NN").
// Batched via blockIdx.z with element strides aB/bB/cB.
// Block tile 128x128x16, 256 threads = 8 warps, warp tile 64x32,
// mma.sync.aligned.m16n8k8.row.col.f32.tf32.tf32.f32
#define BM 128
#define BN 128
#define BK 16
#define LDS_ 20   // BK + 4 pad; (20m+k)%32 covers all 32 banks for frag loads

__device__ __forceinline__ uint32_t f2tf32(float x) {
    uint32_t r;
    asm("cvt.rna.tf32.f32 %0, %1;" : "=r"(r) : "f"(x));
    return r;
}

__device__ __forceinline__ void split_tf32(float x, uint32_t& hi, uint32_t& lo) {
    hi = f2tf32(x);
    lo = f2tf32(x - __uint_as_float(hi));
}

#define MMA_TF32(c, a0, a1, a2, a3, b0, b1)                                     \
    asm volatile(                                                               \
        "mma.sync.aligned.m16n8k8.row.col.f32.tf32.tf32.f32 "                   \
        "{%0,%1,%2,%3}, {%4,%5,%6,%7}, {%8,%9}, {%0,%1,%2,%3};"                 \
        : "+f"((c)[0]), "+f"((c)[1]), "+f"((c)[2]), "+f"((c)[3])                \
        : "r"(a0), "r"(a1), "r"(a2), "r"(a3), "r"(b0), "r"(b1))

template <bool BNT>
__global__ __launch_bounds__(256)
void gemm_tc(const float* __restrict__ A, const float* __restrict__ B,
             float* __restrict__ C, const float* __restrict__ Cadd,
             const float* __restrict__ bias1, const float* __restrict__ bias2,
             int M, int N, int K,
             long long aB, long long bB, long long cB)
{
    __shared__ uint32_t AsH[BM * LDS_];
    __shared__ uint32_t AsL[BM * LDS_];
    __shared__ uint32_t BsH[BN * LDS_];
    __shared__ uint32_t BsL[BN * LDS_];

    const int tid = threadIdx.x;
    const int bx = blockIdx.x, by = blockIdx.y, bz = blockIdx.z;
    const int lane = tid & 31;
    const int w   = tid >> 5;            // 0..7
    const int wr  = w >> 2;              // 0..1 : 64-row half
    const int wc  = w & 3;               // 0..3 : 32-col quarter

    A += (long long)bz * aB + (long long)by * BM * K;
    if (BNT) B += (long long)bz * bB + (long long)bx * BN * K;
    else     B += (long long)bz * bB + bx * BN;
    C += (long long)bz * cB;

    float acc[4][4][4];
    #pragma unroll
    for (int i = 0; i < 4; i++)
        #pragma unroll
        for (int j = 0; j < 4; j++)
            #pragma unroll
            for (int q = 0; q < 4; q++) acc[i][j][q] = 0.f;

    const int g1 = lane >> 2;            // group id 0..7
    const int g2 = lane & 3;             // thread-in-group 0..3

    for (int k0 = 0; k0 < K; k0 += BK) {
        // ---- load A tile 128x16 (k-contiguous), split into tf32 hi/lo ----
        #pragma unroll
        for (int l = 0; l < 2; l++) {
            int f = tid + l * 256;       // float4 slot 0..511
            int r = f >> 2;              // 0..127
            int kg = (f & 3) * 4;        // 0,4,8,12
            float4 v = *(const float4*)(A + (long long)r * K + k0 + kg);
            uint32_t* ph = &AsH[r * LDS_ + kg];
            uint32_t* pl = &AsL[r * LDS_ + kg];
            split_tf32(v.x, ph[0], pl[0]); split_tf32(v.y, ph[1], pl[1]);
            split_tf32(v.z, ph[2], pl[2]); split_tf32(v.w, ph[3], pl[3]);
        }
        // ---- load B tile into [n][k] hi/lo ----
        if (BNT) {
            #pragma unroll
            for (int l = 0; l < 2; l++) {
                int f = tid + l * 256;
                int r = f >> 2;
                int kg = (f & 3) * 4;
                float4 v = *(const float4*)(B + (long long)r * K + k0 + kg);
                uint32_t* ph = &BsH[r * LDS_ + kg];
                uint32_t* pl = &BsL[r * LDS_ + kg];
                split_tf32(v.x, ph[0], pl[0]); split_tf32(v.y, ph[1], pl[1]);
                split_tf32(v.z, ph[2], pl[2]); split_tf32(v.w, ph[3], pl[3]);
            }
        } else {
            #pragma unroll
            for (int l = 0; l < 2; l++) {
                int f = tid + l * 256;
                int r = f >> 5;          // k row 0..15
                int cg = (f & 31) * 4;   // n col 0..124
                float4 v = *(const float4*)(B + (long long)(k0 + r) * N + cg);
                split_tf32(v.x, BsH[(cg + 0) * LDS_ + r], BsL[(cg + 0) * LDS_ + r]);
                split_tf32(v.y, BsH[(cg + 1) * LDS_ + r], BsL[(cg + 1) * LDS_ + r]);
                split_tf32(v.z, BsH[(cg + 2) * LDS_ + r], BsL[(cg + 2) * LDS_ + r]);
                split_tf32(v.w, BsH[(cg + 3) * LDS_ + r], BsL[(cg + 3) * LDS_ + r]);
            }
        }
        __syncthreads();

        #pragma unroll
        for (int ks = 0; ks < BK; ks += 8) {
            const int kk = ks + g2;
            uint32_t aH[4][4], aL[4][4], bH[4][2], bL[4][2];
            #pragma unroll
            for (int mt = 0; mt < 4; mt++) {
                int m0 = wr * 64 + mt * 16 + g1;
                int i00 = m0 * LDS_ + kk, i10 = (m0 + 8) * LDS_ + kk;
                aH[mt][0] = AsH[i00];     aH[mt][1] = AsH[i10];
                aH[mt][2] = AsH[i00 + 4]; aH[mt][3] = AsH[i10 + 4];
                aL[mt][0] = AsL[i00];     aL[mt][1] = AsL[i10];
                aL[mt][2] = AsL[i00 + 4]; aL[mt][3] = AsL[i10 + 4];
            }
            #pragma unroll
            for (int nt = 0; nt < 4; nt++) {
                int n0 = (wc * 32 + nt * 8 + g1) * LDS_ + kk;
                bH[nt][0] = BsH[n0]; bH[nt][1] = BsH[n0 + 4];
                bL[nt][0] = BsL[n0]; bL[nt][1] = BsL[n0 + 4];
            }
            #pragma unroll
            for (int mt = 0; mt < 4; mt++)
                #pragma unroll
                for (int nt = 0; nt < 4; nt++) {
                    float* c = acc[mt][nt];
                    MMA_TF32(c, aH[mt][0], aH[mt][1], aH[mt][2], aH[mt][3],
                             bH[nt][0], bH[nt][1]);
                    MMA_TF32(c, aH[mt][0], aH[mt][1], aH[mt][2], aH[mt][3],
                             bL[nt][0], bL[nt][1]);
                    MMA_TF32(c, aL[mt][0], aL[mt][1], aL[mt][2], aL[mt][3],
                             bH[nt][0], bH[nt][1]);
                }
        }
        __syncthreads();
    }

    // ---- epilogue: fp32 adds, float2 stores ----
    const int gr0 = by * BM + wr * 64;
    const int gc0 = bx * BN + wc * 32;
    #pragma unroll
    for (int mt = 0; mt < 4; mt++) {
        #pragma unroll
        for (int nt = 0; nt < 4; nt++) {
            int row = gr0 + mt * 16 + g1;
            int col = gc0 + nt * 8 + 2 * g2;
            long long i0 = (long long)row * N + col;
            long long i1 = (long long)(row + 8) * N + col;
            float v0 = acc[mt][nt][0], v1 = acc[mt][nt][1];
            float v2 = acc[mt][nt][2], v3 = acc[mt][nt][3];
            if (Cadd) {
                float2 u0 = *(const float2*)(Cadd + i0);
                float2 u1 = *(const float2*)(Cadd + i1);
                v0 += u0.x; v1 += u0.y; v2 += u1.x; v3 += u1.y;
            }
            if (bias1) {
                float bb0 = bias1[col] + bias2[col];
                float bb1 = bias1[col + 1] + bias2[col + 1];
                v0 += bb0; v1 += bb1; v2 += bb0; v3 += bb1;
            }
            *(float2*)(C + i0) = make_float2(v0, v1);
            *(float2*)(C + i1) = make_float2(v2, v3);
        }
    }
}

// ---------------- softmax over rows of 1024 ---------------------------------
__global__ void softmax1024(float* __restrict__ s)
{
    __shared__ float red[8];
    float* p = s + (size_t)blockIdx.x * NKS;
    const int tid = threadIdx.x;           // 256 threads, 4 elems each

    float v[4];
    float m = -1e30f;
    #pragma unroll
    for (int i = 0; i < 4; i++) { v[i] = p[tid + i * 256]; m = fmaxf(m, v[i]); }
    #pragma unroll
    for (int o = 16; o > 0; o >>= 1) m = fmaxf(m, __shfl_xor_sync(0xffffffffu, m, o));
    if ((tid & 31) == 0) red[tid >> 5] = m;
    __syncthreads();
    float bm = -1e30f;
    #pragma unroll
    for (int i = 0; i < 8; i++) bm = fmaxf(bm, red[i]);
    __syncthreads();

    float sum = 0.f;
    #pragma unroll
    for (int i = 0; i < 4; i++) { v[i] = __expf(v[i] - bm); sum += v[i]; }
    #pragma unroll
    for (int o = 16; o > 0; o >>= 1) sum += __shfl_xor_sync(0xffffffffu, sum, o);
    if ((tid & 31) == 0) red[tid >> 5] = sum;
    __syncthreads();
    float tot = 0.f;
    #pragma unroll
    for (int i = 0; i < 8; i++) tot += red[i];
    float inv = 1.f / tot;
    #pragma unroll
    for (int i = 0; i < 4; i++) p[tid + i * 256] = v[i] * inv;
}

// ---------------- fused LSTM pointwise --------------------------------------
__global__ void lstm_pw(const float* __restrict__ gates, const float* __restrict__ x,
                        const float* __restrict__ r, float* __restrict__ h,
                        float* __restrict__ c)
{
    long long idx = (long long)blockIdx.x * blockDim.x + threadIdx.x;
    int m = (int)(idx >> 9);               // /512
    int e = (int)(idx & 511);
    const float* grow = gates + (long long)m * G4;
    float gi = grow[e];
    float gf = grow[512 + e];
    float gg = grow[1024 + e];
    float go = grow[1536 + e];
    float cp = c[idx];
    float si = 1.f / (1.f + __expf(-gi));
    float sf = 1.f / (1.f + __expf(-gf));
    float so = 1.f / (1.f + __expf(-go));
    float cn = sf * cp + si * tanhf(gg);
    float hn = so * tanhf(cn) + x[idx] + r[idx];
    c[idx] = cn;
    h[idx] = hn;
}

// ---------------- launch ----------------------------------------------------
extern "C" void kernel_launch(void* const* d_in, const int* in_sizes, int n_in,
                              void* d_out, int out_size)
{
    const float* targets = (const float*)d_in[0];   // [8192, 512]
    const float* sup     = (const float*)d_in[1];   // [64, 1024, 512]
    const float* W_ih    = (const float*)d_in[2];   // [2048, 512]
    const float* W_hh    = (const float*)d_in[3];   // [2048, 512]
    const float* b_ih    = (const float*)d_in[4];   // [2048]
    const float* b_hh    = (const float*)d_in[5];   // [2048]
    float* out = (float*)d_out;

    float *xW, *gates, *h, *c, *scores, *r;
    cudaGetSymbolAddress((void**)&xW, g_xW);
    cudaGetSymbolAddress((void**)&gates, g_gates);
    cudaGetSymbolAddress((void**)&h, g_h);
    cudaGetSymbolAddress((void**)&c, g_c);
    cudaGetSymbolAddress((void**)&scores, g_scores);
    cudaGetSymbolAddress((void**)&r, g_r);

    cudaMemsetAsync(h, 0, (size_t)M_ROWS * EDIM * sizeof(float));
    cudaMemsetAsync(c, 0, (size_t)M_ROWS * EDIM * sizeof(float));

    dim3 blk(256);

    // xW = x @ W_ih^T + b_ih + b_hh   (loop-invariant, computed once)
    gemm_tc<true><<<dim3(G4 / BN, M_ROWS / BM, 1), blk>>>(
        targets, W_ih, xW, nullptr, b_ih, b_hh, M_ROWS, G4, EDIM, 0, 0, 0);

    for (int s = 0; s < NSTEPS; s++) {
        // gates = xW + h_prev @ W_hh^T
        gemm_tc<true><<<dim3(G4 / BN, M_ROWS / BM, 1), blk>>>(
            h, W_hh, gates, xW, nullptr, nullptr, M_ROWS, G4, EDIM, 0, 0, 0);

        // scores[b] = h_prev[b] @ sup[b]^T   (batched NT, 64 batches)
        gemm_tc<true><<<dim3(NKS / BN, 128 / BM, NBATCH), blk>>>(
            h, sup, scores, nullptr, nullptr, nullptr,
            128, NKS, EDIM,
            (long long)128 * EDIM, (long long)NKS * EDIM, (long long)128 * NKS);

        // softmax over the 1024 support slots
        softmax1024<<<M_ROWS, 256>>>(scores);

        // r[b] = attn[b] @ sup[b]   (batched NN)
        gemm_tc<false><<<dim3(EDIM / BN, 128 / BM, NBATCH), blk>>>(
            scores, sup, r, nullptr, nullptr, nullptr,
            128, EDIM, NKS,
            (long long)128 * NKS, (long long)NKS * EDIM, (long long)128 * EDIM);

        // pointwise LSTM cell + residual adds
        lstm_pw<<<(M_ROWS * EDIM) / 256, 256>>>(gates, targets, r, h, c);
    }

    cudaMemcpyAsync(out, h, (size_t)M_ROWS * EDIM * sizeof(float),
                    cudaMemcpyDeviceToDevice);
}